// round 6
// baseline (speedup 1.0000x reference)
#include <cuda_runtime.h>
#include <cuda_bf16.h>
#include <cstdint>

// Problem dims
#define B_ 16
#define L_ 512
#define H_ 8
#define E_ 64
#define BH_ (B_ * H_)          // 128

// ===================== helpers =====================
__device__ __forceinline__ uint32_t smem_u32(const void* p) {
    uint32_t a;
    asm("{ .reg .u64 t; cvta.to.shared.u64 t, %1; cvt.u32.u64 %0, t; }"
        : "=r"(a) : "l"(p));
    return a;
}
__device__ __forceinline__ uint32_t bf16x2_of(float v0, float v1) {
    uint32_t r;
    asm("cvt.rn.bf16x2.f32 %0, %1, %2;" : "=r"(r) : "f"(v1), "f"(v0));
    return r;
}
__device__ __forceinline__ uint32_t lds32(uint32_t addr) {
    uint32_t v;
    asm volatile("ld.shared.b32 %0, [%1];" : "=r"(v) : "r"(addr));
    return v;
}
__device__ __forceinline__ void sts64(uint32_t addr, float c0, float c1) {
    asm volatile("st.shared.v2.f32 [%0], {%1,%2};" :: "r"(addr), "f"(c0), "f"(c1) : "memory");
}
__device__ __forceinline__ void mma16816(float* c, const uint32_t* a, const uint32_t* b) {
    asm volatile(
        "mma.sync.aligned.m16n8k16.row.col.f32.bf16.bf16.f32 "
        "{%0,%1,%2,%3}, {%4,%5,%6,%7}, {%8,%9}, {%0,%1,%2,%3};"
        : "+f"(c[0]), "+f"(c[1]), "+f"(c[2]), "+f"(c[3])
        : "r"(a[0]), "r"(a[1]), "r"(a[2]), "r"(a[3]), "r"(b[0]), "r"(b[1]));
}
__device__ __forceinline__ float exp_acc(float x) {
    float m = __fmul_rn(x, 1.4426950408889634f);
    float t = __fmaf_rn(x, 1.925962991e-8f, m);
    float r;
    asm("ex2.approx.ftz.f32 %0, %1;" : "=f"(r) : "f"(t));
    return r;
}
__device__ __forceinline__ void split_store4(char* smem, uint32_t offHi, uint32_t offLo, float4 v) {
    uint32_t h01 = bf16x2_of(v.x, v.y);
    uint32_t h23 = bf16x2_of(v.z, v.w);
    float l0 = v.x - __uint_as_float(h01 << 16);
    float l1 = v.y - __uint_as_float(h01 & 0xFFFF0000u);
    float l2 = v.z - __uint_as_float(h23 << 16);
    float l3 = v.w - __uint_as_float(h23 & 0xFFFF0000u);
    *(uint2*)(smem + offHi) = make_uint2(h01, h23);
    *(uint2*)(smem + offLo) = make_uint2(bf16x2_of(l0, l1), bf16x2_of(l2, l3));
}

// ======================================================================
// Kernel 1 (fused): series[bh, l, :] = softmax_s( (Q/8)[l,:] . K[s,:] )
// CTA: 64 l-rows x 512 s-cols, K=64. 512 thr, warp grid 4m x 4n,
// warp tile 16x128. All of K(bh) in smem (hi/lo), Q tile in smem.
// ======================================================================
#define F_ST   72                 // bf16 row stride (144 B, conflict-free)
#define F_QHI  0                  // 64*144  = 9216
#define F_QLO  9216
#define F_KHI  18432              // 512*144 = 73728
#define F_KLO  92160
#define F_RED0 165888             // 64 rows * 4 wn * 4B = 1024
#define F_RED1 166912
#define F_SMEM 167936

__global__ void __launch_bounds__(512, 1)
qk_softmax_kernel(const float* __restrict__ q, const float* __restrict__ k,
                  float* __restrict__ series)
{
    extern __shared__ char smem[];
    const uint32_t sb = smem_u32(smem);
    const int tid  = threadIdx.x;
    const int wid  = tid >> 5;
    const int lane = tid & 31;
    const int wm   = wid >> 2;       // 4 m-warps (16 rows each)
    const int wn   = wid & 3;        // 4 n-warps (128 cols each)
    const int r    = lane >> 2;
    const int qc   = lane & 3;

    const int bh = blockIdx.y;
    const int b  = bh >> 3;
    const int h  = bh & 7;
    const int lt = blockIdx.x;       // 8 tiles of 64 rows

    const float* qbase = q + (size_t)(b * L_ + lt * 64) * (H_ * E_) + h * E_;
    const float* kbase = k + (size_t)(b * L_) * (H_ * E_) + h * E_;

    // Q tile 64x64 (scaled by 1/8), split hi/lo
#pragma unroll
    for (int i = tid; i < 1024; i += 512) {
        int row = i >> 4, e4 = i & 15;
        uint32_t off = (uint32_t)row * (F_ST * 2) + e4 * 8;
        float4 va = *(const float4*)(qbase + (size_t)row * (H_ * E_) + e4 * 4);
        va.x *= 0.125f; va.y *= 0.125f; va.z *= 0.125f; va.w *= 0.125f;
        split_store4(smem, F_QHI + off, F_QLO + off, va);
    }
    // K full 512x64, split hi/lo
#pragma unroll
    for (int i = tid; i < 8192; i += 512) {
        int row = i >> 4, e4 = i & 15;
        uint32_t off = (uint32_t)row * (F_ST * 2) + e4 * 8;
        float4 vb = *(const float4*)(kbase + (size_t)row * (H_ * E_) + e4 * 4);
        split_store4(smem, F_KHI + off, F_KLO + off, vb);
    }
    __syncthreads();

    float acc[16][4];
#pragma unroll
    for (int nb = 0; nb < 16; nb++)
#pragma unroll
        for (int x = 0; x < 4; x++) acc[nb][x] = 0.f;

    const uint32_t abase[3] = {sb + F_QHI, sb + F_QHI, sb + F_QLO};
    const uint32_t bbase[3] = {sb + F_KHI, sb + F_KLO, sb + F_KHI};

#pragma unroll
    for (int pr = 0; pr < 3; pr++) {
        uint32_t Ab = abase[pr], Bb = bbase[pr];
#pragma unroll
        for (int ks = 0; ks < 4; ks++) {
            uint32_t kByte = ks * 32 + qc * 4;
            uint32_t a[4];
            uint32_t ad = Ab + (uint32_t)(wm * 16 + r) * (F_ST * 2) + kByte;
            a[0] = lds32(ad);
            a[1] = lds32(ad + 8 * F_ST * 2);
            a[2] = lds32(ad + 16);
            a[3] = lds32(ad + 8 * F_ST * 2 + 16);
#pragma unroll
            for (int nb = 0; nb < 16; nb++) {
                uint32_t bd = Bb + (uint32_t)(wn * 128 + nb * 8 + r) * (F_ST * 2) + kByte;
                uint32_t bf[2];
                bf[0] = lds32(bd);
                bf[1] = lds32(bd + 16);
                mma16816(acc[nb], a, bf);
            }
        }
    }

    // ---------- softmax over full 512 cols ----------
    const int row0 = wm * 16 + r;
    const int row1 = row0 + 8;

    float mx0 = -1e30f, mx1 = -1e30f;
#pragma unroll
    for (int nb = 0; nb < 16; nb++) {
        mx0 = fmaxf(mx0, fmaxf(acc[nb][0], acc[nb][1]));
        mx1 = fmaxf(mx1, fmaxf(acc[nb][2], acc[nb][3]));
    }
#pragma unroll
    for (int o = 1; o <= 2; o <<= 1) {
        mx0 = fmaxf(mx0, __shfl_xor_sync(0xffffffffu, mx0, o));
        mx1 = fmaxf(mx1, __shfl_xor_sync(0xffffffffu, mx1, o));
    }
    if (qc == 0) {
        *(float*)(smem + F_RED0 + (row0 * 4 + wn) * 4) = mx0;
        *(float*)(smem + F_RED0 + (row1 * 4 + wn) * 4) = mx1;
    }
    __syncthreads();
    {
        const float* rd = (const float*)(smem + F_RED0);
        mx0 = fmaxf(fmaxf(rd[row0 * 4 + 0], rd[row0 * 4 + 1]),
                    fmaxf(rd[row0 * 4 + 2], rd[row0 * 4 + 3]));
        mx1 = fmaxf(fmaxf(rd[row1 * 4 + 0], rd[row1 * 4 + 1]),
                    fmaxf(rd[row1 * 4 + 2], rd[row1 * 4 + 3]));
    }

    float s0 = 0.f, s1 = 0.f;
#pragma unroll
    for (int nb = 0; nb < 16; nb++) {
        acc[nb][0] = exp_acc(acc[nb][0] - mx0); s0 += acc[nb][0];
        acc[nb][1] = exp_acc(acc[nb][1] - mx0); s0 += acc[nb][1];
        acc[nb][2] = exp_acc(acc[nb][2] - mx1); s1 += acc[nb][2];
        acc[nb][3] = exp_acc(acc[nb][3] - mx1); s1 += acc[nb][3];
    }
#pragma unroll
    for (int o = 1; o <= 2; o <<= 1) {
        s0 += __shfl_xor_sync(0xffffffffu, s0, o);
        s1 += __shfl_xor_sync(0xffffffffu, s1, o);
    }
    if (qc == 0) {
        *(float*)(smem + F_RED1 + (row0 * 4 + wn) * 4) = s0;
        *(float*)(smem + F_RED1 + (row1 * 4 + wn) * 4) = s1;
    }
    __syncthreads();
    {
        const float* rd = (const float*)(smem + F_RED1);
        s0 = (rd[row0 * 4 + 0] + rd[row0 * 4 + 1]) + (rd[row0 * 4 + 2] + rd[row0 * 4 + 3]);
        s1 = (rd[row1 * 4 + 0] + rd[row1 * 4 + 1]) + (rd[row1 * 4 + 2] + rd[row1 * 4 + 3]);
    }
    const float inv0 = __fdiv_rn(1.f, s0);
    const float inv1 = __fdiv_rn(1.f, s1);

    // write series: st.v2 — quad lanes cover whole 32B sectors
    float* o0 = series + ((size_t)bh * L_ + lt * 64 + row0) * L_ + wn * 128 + qc * 2;
    float* o1 = series + ((size_t)bh * L_ + lt * 64 + row1) * L_ + wn * 128 + qc * 2;
#pragma unroll
    for (int nb = 0; nb < 16; nb++) {
        *(float2*)(o0 + nb * 8) = make_float2(acc[nb][0] * inv0, acc[nb][1] * inv0);
        *(float2*)(o1 + nb * 8) = make_float2(acc[nb][2] * inv1, acc[nb][3] * inv1);
    }
}

// ======================================================================
// Kernel 2: prior + sigma_full only (pure streaming writes).
// One warp per row (b,h,l). 8 warps per block.
// ======================================================================
__global__ void __launch_bounds__(256) prior_sig_kernel(
    const float* __restrict__ sigma,
    float* __restrict__ prior,
    float* __restrict__ sigf)
{
    const int w    = threadIdx.x >> 5;
    const int lane = threadIdx.x & 31;
    const int r    = blockIdx.x * 8 + w;
    const int bh   = r >> 9;
    const int l    = r & 511;
    const int b    = bh >> 3;
    const int h    = bh & 7;

    float sg;
    if (lane == 0) {
        double xd = (double)sigma[((size_t)b * L_ + l) * H_ + h];
        double sd = 1.0 / (1.0 + exp(-5.0 * xd));
        float sgm = (float)(sd + 1e-5);
        double P  = exp2((double)sgm * 1.5849625007211562);  // 3^sgm
        sg = (float)P - 1.0f;
    }
    sg = __shfl_sync(0xffffffffu, sg, 0);

    const float c    = __fdiv_rn(0.3989422804014327f, sg);
    const float sg2  = __fmul_rn(sg, sg);
    const float den  = __fmul_rn(2.0f, sg2);
    const float rinv = __fdiv_rn(1.0f, den);

    float* pr = prior + (size_t)r * L_;
    float* sf = sigf + (size_t)r * L_;
    const float4 sgv = make_float4(sg, sg, sg, sg);
#pragma unroll
    for (int t = 0; t < 4; t++) {
        int j0 = t * 128 + lane * 4;
        float d0 = (float)(l - j0);
        float d1 = (float)(l - (j0 + 1));
        float d2 = (float)(l - (j0 + 2));
        float d3 = (float)(l - (j0 + 3));
        float4 pv;
        pv.x = __fmul_rn(c, exp_acc(-__fmul_rn(__fmul_rn(d0, d0), rinv)));
        pv.y = __fmul_rn(c, exp_acc(-__fmul_rn(__fmul_rn(d1, d1), rinv)));
        pv.z = __fmul_rn(c, exp_acc(-__fmul_rn(__fmul_rn(d2, d2), rinv)));
        pv.w = __fmul_rn(c, exp_acc(-__fmul_rn(__fmul_rn(d3, d3), rinv)));
        *(float4*)(pr + j0) = pv;
        *(float4*)(sf + j0) = sgv;
    }
}

// ======================================================================
// Kernel 3 (HMMA): V[b,l,h,d] = sum_s P[bh,l,s] * values[b,s,h,d]
// (unchanged from R5)
// ======================================================================
#define PV_ST 72
#define PV_PHI 0
#define PV_PLO 18432
#define PV_VHI 36864
#define PV_VLO 46080
#define PV_SMEM 55296

__global__ void __launch_bounds__(256, 2)
pv_mma_kernel(const float* __restrict__ p, const float* __restrict__ v,
              float* __restrict__ out)
{
    extern __shared__ char smem[];
    const uint32_t sb = smem_u32(smem);
    const int tid = threadIdx.x;
    const int wid = tid >> 5;
    const int lane = tid & 31;

    const int bh = blockIdx.y;
    const int b  = bh >> 3;
    const int h  = bh & 7;
    const int mt = blockIdx.x;

    const float* prow  = p + ((size_t)bh * L_ + mt * 128) * L_;
    const float* vbase = v + (size_t)b * L_ * H_ * E_ + h * E_;

    const int wm = wid & 1;
    const int wn = wid >> 1;
    const int r  = lane >> 2;
    const int kkB = (lane & 3) * 4;

    float acc[4][2][4];
#pragma unroll
    for (int mb = 0; mb < 4; mb++)
#pragma unroll
        for (int nb = 0; nb < 2; nb++)
#pragma unroll
            for (int x = 0; x < 4; x++) acc[mb][nb][x] = 0.f;

    const uint32_t abase[3] = {sb + PV_PHI, sb + PV_PHI, sb + PV_PLO};
    const uint32_t bbase[3] = {sb + PV_VHI, sb + PV_VLO, sb + PV_VHI};

    for (int c = 0; c < 8; c++) {
#pragma unroll
        for (int i = tid; i < 2048; i += 256) {
            int row = i >> 4, s4 = i & 15;
            uint32_t off = (uint32_t)row * (PV_ST * 2) + s4 * 8;
            float4 va = *(const float4*)(prow + (size_t)row * L_ + c * 64 + s4 * 4);
            split_store4(smem, PV_PHI + off, PV_PLO + off, va);
        }
#pragma unroll
        for (int i = tid; i < 1024; i += 256) {
            int s = i >> 4, d4 = i & 15;
            float4 vv = *(const float4*)(vbase + (size_t)(c * 64 + s) * (H_ * E_) + d4 * 4);
            float xs[4] = {vv.x, vv.y, vv.z, vv.w};
#pragma unroll
            for (int j = 0; j < 4; j++) {
                __nv_bfloat16 hb = __float2bfloat16(xs[j]);
                float hf = __bfloat162float(hb);
                __nv_bfloat16 lb = __float2bfloat16(xs[j] - hf);
                uint32_t off = (uint32_t)(d4 * 4 + j) * (PV_ST * 2) + s * 2;
                *(__nv_bfloat16*)(smem + PV_VHI + off) = hb;
                *(__nv_bfloat16*)(smem + PV_VLO + off) = lb;
            }
        }
        __syncthreads();

#pragma unroll
        for (int pr = 0; pr < 3; pr++) {
            uint32_t Ab = abase[pr], Bb = bbase[pr];
#pragma unroll
            for (int ks = 0; ks < 4; ks++) {
                uint32_t kByte = ks * 32 + kkB;
                uint32_t a[4][4];
#pragma unroll
                for (int mb = 0; mb < 4; mb++) {
                    uint32_t ad = Ab + (uint32_t)(wm * 64 + mb * 16 + r) * (PV_ST * 2) + kByte;
                    a[mb][0] = lds32(ad);
                    a[mb][1] = lds32(ad + 8 * PV_ST * 2);
                    a[mb][2] = lds32(ad + 16);
                    a[mb][3] = lds32(ad + 8 * PV_ST * 2 + 16);
                }
                uint32_t bf[2][2];
#pragma unroll
                for (int nb = 0; nb < 2; nb++) {
                    uint32_t bd = Bb + (uint32_t)(wn * 16 + nb * 8 + r) * (PV_ST * 2) + kByte;
                    bf[nb][0] = lds32(bd);
                    bf[nb][1] = lds32(bd + 16);
                }
#pragma unroll
                for (int mb = 0; mb < 4; mb++)
#pragma unroll
                    for (int nb = 0; nb < 2; nb++)
                        mma16816(acc[mb][nb], a[mb], bf[nb]);
            }
        }
        __syncthreads();
    }

#pragma unroll
    for (int mb = 0; mb < 4; mb++)
#pragma unroll
        for (int nb = 0; nb < 2; nb++) {
            uint32_t row = wm * 64 + mb * 16 + r;
            uint32_t col = wn * 16 + nb * 8 + (lane & 3) * 2;
            uint32_t ad = sb + (row * 68 + col) * 4;
            sts64(ad, acc[mb][nb][0], acc[mb][nb][1]);
            sts64(ad + 8 * 68 * 4, acc[mb][nb][2], acc[mb][nb][3]);
        }
    __syncthreads();

#pragma unroll
    for (int i = tid; i < 2048; i += 256) {
        int row = i >> 4, c4 = i & 15;
        int l = mt * 128 + row;
        float4 vv = *(const float4*)(smem + (row * 68 + c4 * 4) * 4);
        *(float4*)(out + (((size_t)b * L_ + l) * H_ + h) * E_ + c4 * 4) = vv;
    }
}

// ======================================================================
extern "C" void kernel_launch(void* const* d_in, const int* in_sizes, int n_in,
                              void* d_out, int out_size)
{
    const float* q     = (const float*)d_in[0];
    const float* k     = (const float*)d_in[1];
    const float* v     = (const float*)d_in[2];
    const float* sigma = (const float*)d_in[3];

    float* out    = (float*)d_out;
    float* Vout   = out;                                        // [B,L,H,E]
    float* series = Vout + (size_t)B_ * L_ * H_ * E_;           // [B,H,L,L]
    float* prior  = series + (size_t)BH_ * L_ * L_;             // [B,H,L,L]
    float* sigf   = prior + (size_t)BH_ * L_ * L_;              // [B,H,L,L]

    cudaFuncSetAttribute(qk_softmax_kernel, cudaFuncAttributeMaxDynamicSharedMemorySize, F_SMEM);
    cudaFuncSetAttribute(pv_mma_kernel, cudaFuncAttributeMaxDynamicSharedMemorySize, PV_SMEM);

    dim3 g1(8, BH_);
    qk_softmax_kernel<<<g1, 512, F_SMEM>>>(q, k, series);

    prior_sig_kernel<<<(BH_ * L_) / 8, 256>>>(sigma, prior, sigf);

    dim3 g2(4, BH_);
    pv_mma_kernel<<<g2, 256, PV_SMEM>>>(series, v, Vout);
}

// round 7
// speedup vs baseline: 1.7859x; 1.7859x over previous
#include <cuda_runtime.h>
#include <cuda_bf16.h>
#include <cstdint>

// Problem dims
#define B_ 16
#define L_ 512
#define H_ 8
#define E_ 64
#define BH_ (B_ * H_)          // 128

// precomputed bandwidth per (bh, l) row
__device__ float g_sg[BH_ * L_];

// ===================== helpers =====================
__device__ __forceinline__ uint32_t smem_u32(const void* p) {
    uint32_t a;
    asm("{ .reg .u64 t; cvta.to.shared.u64 t, %1; cvt.u32.u64 %0, t; }"
        : "=r"(a) : "l"(p));
    return a;
}
__device__ __forceinline__ uint32_t bf16x2_of(float v0, float v1) {
    uint32_t r;
    asm("cvt.rn.bf16x2.f32 %0, %1, %2;" : "=r"(r) : "f"(v1), "f"(v0));
    return r;
}
__device__ __forceinline__ uint32_t lds32(uint32_t addr) {
    uint32_t v;
    asm volatile("ld.shared.b32 %0, [%1];" : "=r"(v) : "r"(addr));
    return v;
}
__device__ __forceinline__ void mma16816(float* c, const uint32_t* a, const uint32_t* b) {
    asm volatile(
        "mma.sync.aligned.m16n8k16.row.col.f32.bf16.bf16.f32 "
        "{%0,%1,%2,%3}, {%4,%5,%6,%7}, {%8,%9}, {%0,%1,%2,%3};"
        : "+f"(c[0]), "+f"(c[1]), "+f"(c[2]), "+f"(c[3])
        : "r"(a[0]), "r"(a[1]), "r"(a[2]), "r"(a[3]), "r"(b[0]), "r"(b[1]));
}
__device__ __forceinline__ float exp_acc(float x) {
    float m = __fmul_rn(x, 1.4426950408889634f);
    float t = __fmaf_rn(x, 1.925962991e-8f, m);
    float r;
    asm("ex2.approx.ftz.f32 %0, %1;" : "=f"(r) : "f"(t));
    return r;
}
__device__ __forceinline__ void split_store4(char* smem, uint32_t offHi, uint32_t offLo, float4 v) {
    uint32_t h01 = bf16x2_of(v.x, v.y);
    uint32_t h23 = bf16x2_of(v.z, v.w);
    float l0 = v.x - __uint_as_float(h01 << 16);
    float l1 = v.y - __uint_as_float(h01 & 0xFFFF0000u);
    float l2 = v.z - __uint_as_float(h23 << 16);
    float l3 = v.w - __uint_as_float(h23 & 0xFFFF0000u);
    *(uint2*)(smem + offHi) = make_uint2(h01, h23);
    *(uint2*)(smem + offLo) = make_uint2(bf16x2_of(l0, l1), bf16x2_of(l2, l3));
}
// split a float2 into hi bf16x2 and lo bf16x2
__device__ __forceinline__ void split2(float2 v, uint32_t& hi, uint32_t& lo) {
    hi = bf16x2_of(v.x, v.y);
    float l0 = v.x - __uint_as_float(hi << 16);
    float l1 = v.y - __uint_as_float(hi & 0xFFFF0000u);
    lo = bf16x2_of(l0, l1);
}

// ======================================================================
// Kernel 0: precompute sg per (bh,l) row. Double-precision 3^s.
// ======================================================================
__global__ void __launch_bounds__(256) sig_precompute_kernel(const float* __restrict__ sigma)
{
    int idx = blockIdx.x * 256 + threadIdx.x;     // 0..65535
    int bh = idx >> 9, l = idx & 511;
    int b = bh >> 3, h = bh & 7;
    double xd = (double)sigma[((size_t)b * L_ + l) * H_ + h];
    double sd = 1.0 / (1.0 + exp(-5.0 * xd));
    float sgm = (float)(sd + 1e-5);
    double P  = exp2((double)sgm * 1.5849625007211562);  // 3^sgm
    g_sg[idx] = (float)P - 1.0f;
}

// ======================================================================
// Kernel 1 (fused): series = softmax(QK^T/8)   [unchanged from R6]
// ======================================================================
#define F_ST   72
#define F_QHI  0
#define F_QLO  9216
#define F_KHI  18432
#define F_KLO  92160
#define F_RED0 165888
#define F_RED1 166912
#define F_SMEM 167936

__global__ void __launch_bounds__(512, 1)
qk_softmax_kernel(const float* __restrict__ q, const float* __restrict__ k,
                  float* __restrict__ series)
{
    extern __shared__ char smem[];
    const uint32_t sb = smem_u32(smem);
    const int tid  = threadIdx.x;
    const int wid  = tid >> 5;
    const int lane = tid & 31;
    const int wm   = wid >> 2;
    const int wn   = wid & 3;
    const int r    = lane >> 2;
    const int qc   = lane & 3;

    const int bh = blockIdx.y;
    const int b  = bh >> 3;
    const int h  = bh & 7;
    const int lt = blockIdx.x;

    const float* qbase = q + (size_t)(b * L_ + lt * 64) * (H_ * E_) + h * E_;
    const float* kbase = k + (size_t)(b * L_) * (H_ * E_) + h * E_;

#pragma unroll
    for (int i = tid; i < 1024; i += 512) {
        int row = i >> 4, e4 = i & 15;
        uint32_t off = (uint32_t)row * (F_ST * 2) + e4 * 8;
        float4 va = *(const float4*)(qbase + (size_t)row * (H_ * E_) + e4 * 4);
        va.x *= 0.125f; va.y *= 0.125f; va.z *= 0.125f; va.w *= 0.125f;
        split_store4(smem, F_QHI + off, F_QLO + off, va);
    }
#pragma unroll
    for (int i = tid; i < 8192; i += 512) {
        int row = i >> 4, e4 = i & 15;
        uint32_t off = (uint32_t)row * (F_ST * 2) + e4 * 8;
        float4 vb = *(const float4*)(kbase + (size_t)row * (H_ * E_) + e4 * 4);
        split_store4(smem, F_KHI + off, F_KLO + off, vb);
    }
    __syncthreads();

    float acc[16][4];
#pragma unroll
    for (int nb = 0; nb < 16; nb++)
#pragma unroll
        for (int x = 0; x < 4; x++) acc[nb][x] = 0.f;

    const uint32_t abase[3] = {sb + F_QHI, sb + F_QHI, sb + F_QLO};
    const uint32_t bbase[3] = {sb + F_KHI, sb + F_KLO, sb + F_KHI};

#pragma unroll
    for (int pr = 0; pr < 3; pr++) {
        uint32_t Ab = abase[pr], Bb = bbase[pr];
#pragma unroll
        for (int ks = 0; ks < 4; ks++) {
            uint32_t kByte = ks * 32 + qc * 4;
            uint32_t a[4];
            uint32_t ad = Ab + (uint32_t)(wm * 16 + r) * (F_ST * 2) + kByte;
            a[0] = lds32(ad);
            a[1] = lds32(ad + 8 * F_ST * 2);
            a[2] = lds32(ad + 16);
            a[3] = lds32(ad + 8 * F_ST * 2 + 16);
#pragma unroll
            for (int nb = 0; nb < 16; nb++) {
                uint32_t bd = Bb + (uint32_t)(wn * 128 + nb * 8 + r) * (F_ST * 2) + kByte;
                uint32_t bf[2];
                bf[0] = lds32(bd);
                bf[1] = lds32(bd + 16);
                mma16816(acc[nb], a, bf);
            }
        }
    }

    const int row0 = wm * 16 + r;
    const int row1 = row0 + 8;

    float mx0 = -1e30f, mx1 = -1e30f;
#pragma unroll
    for (int nb = 0; nb < 16; nb++) {
        mx0 = fmaxf(mx0, fmaxf(acc[nb][0], acc[nb][1]));
        mx1 = fmaxf(mx1, fmaxf(acc[nb][2], acc[nb][3]));
    }
#pragma unroll
    for (int o = 1; o <= 2; o <<= 1) {
        mx0 = fmaxf(mx0, __shfl_xor_sync(0xffffffffu, mx0, o));
        mx1 = fmaxf(mx1, __shfl_xor_sync(0xffffffffu, mx1, o));
    }
    if (qc == 0) {
        *(float*)(smem + F_RED0 + (row0 * 4 + wn) * 4) = mx0;
        *(float*)(smem + F_RED0 + (row1 * 4 + wn) * 4) = mx1;
    }
    __syncthreads();
    {
        const float* rd = (const float*)(smem + F_RED0);
        mx0 = fmaxf(fmaxf(rd[row0 * 4 + 0], rd[row0 * 4 + 1]),
                    fmaxf(rd[row0 * 4 + 2], rd[row0 * 4 + 3]));
        mx1 = fmaxf(fmaxf(rd[row1 * 4 + 0], rd[row1 * 4 + 1]),
                    fmaxf(rd[row1 * 4 + 2], rd[row1 * 4 + 3]));
    }

    float s0 = 0.f, s1 = 0.f;
#pragma unroll
    for (int nb = 0; nb < 16; nb++) {
        acc[nb][0] = exp_acc(acc[nb][0] - mx0); s0 += acc[nb][0];
        acc[nb][1] = exp_acc(acc[nb][1] - mx0); s0 += acc[nb][1];
        acc[nb][2] = exp_acc(acc[nb][2] - mx1); s1 += acc[nb][2];
        acc[nb][3] = exp_acc(acc[nb][3] - mx1); s1 += acc[nb][3];
    }
#pragma unroll
    for (int o = 1; o <= 2; o <<= 1) {
        s0 += __shfl_xor_sync(0xffffffffu, s0, o);
        s1 += __shfl_xor_sync(0xffffffffu, s1, o);
    }
    if (qc == 0) {
        *(float*)(smem + F_RED1 + (row0 * 4 + wn) * 4) = s0;
        *(float*)(smem + F_RED1 + (row1 * 4 + wn) * 4) = s1;
    }
    __syncthreads();
    {
        const float* rd = (const float*)(smem + F_RED1);
        s0 = (rd[row0 * 4 + 0] + rd[row0 * 4 + 1]) + (rd[row0 * 4 + 2] + rd[row0 * 4 + 3]);
        s1 = (rd[row1 * 4 + 0] + rd[row1 * 4 + 1]) + (rd[row1 * 4 + 2] + rd[row1 * 4 + 3]);
    }
    const float inv0 = __fdiv_rn(1.f, s0);
    const float inv1 = __fdiv_rn(1.f, s1);

    float* o0 = series + ((size_t)bh * L_ + lt * 64 + row0) * L_ + wn * 128 + qc * 2;
    float* o1 = series + ((size_t)bh * L_ + lt * 64 + row1) * L_ + wn * 128 + qc * 2;
#pragma unroll
    for (int nb = 0; nb < 16; nb++) {
        *(float2*)(o0 + nb * 8) = make_float2(acc[nb][0] * inv0, acc[nb][1] * inv0);
        *(float2*)(o1 + nb * 8) = make_float2(acc[nb][2] * inv1, acc[nb][3] * inv1);
    }
}

// ======================================================================
// Kernel 2: prior + sigma_full (pure fp32, sg precomputed).
// ======================================================================
__global__ void __launch_bounds__(256) prior_sig_kernel(
    float* __restrict__ prior,
    float* __restrict__ sigf)
{
    const int w    = threadIdx.x >> 5;
    const int lane = threadIdx.x & 31;
    const int r    = blockIdx.x * 8 + w;
    const int l    = r & 511;

    const float sg = g_sg[r];
    const float c    = __fdiv_rn(0.3989422804014327f, sg);
    const float sg2  = __fmul_rn(sg, sg);
    const float den  = __fmul_rn(2.0f, sg2);
    const float rinv = __fdiv_rn(1.0f, den);

    float* pr = prior + (size_t)r * L_;
    float* sf = sigf + (size_t)r * L_;
    const float4 sgv = make_float4(sg, sg, sg, sg);
#pragma unroll
    for (int t = 0; t < 4; t++) {
        int j0 = t * 128 + lane * 4;
        float d0 = (float)(l - j0);
        float d1 = (float)(l - (j0 + 1));
        float d2 = (float)(l - (j0 + 2));
        float d3 = (float)(l - (j0 + 3));
        float4 pv;
        pv.x = __fmul_rn(c, exp_acc(-__fmul_rn(__fmul_rn(d0, d0), rinv)));
        pv.y = __fmul_rn(c, exp_acc(-__fmul_rn(__fmul_rn(d1, d1), rinv)));
        pv.z = __fmul_rn(c, exp_acc(-__fmul_rn(__fmul_rn(d2, d2), rinv)));
        pv.w = __fmul_rn(c, exp_acc(-__fmul_rn(__fmul_rn(d3, d3), rinv)));
        *(float4*)(pr + j0) = pv;
        *(float4*)(sf + j0) = sgv;
    }
}

// ======================================================================
// Kernel 3 (rebuilt): V[b,l,h,d] = sum_s P[bh,l,s] * values[b,s,h,d]
// CTA: 256 l-rows x 64 d, 512 thr (16 warps, m16 each, n=64 full).
// V(bh) fully in smem transposed+split hi/lo; P A-frags straight from
// global into registers (quad float2 = full 32B sectors), split in-reg.
// No syncthreads in mainloop.
// ======================================================================
#define PVB_ST  1040              // Vt row stride bytes (520 bf16) - conflict free
#define PVB_HI  0                 // 64 * 1040 = 66560
#define PVB_LO  66560
#define PVB_SMEM 133120

__global__ void __launch_bounds__(512, 1)
pv2_kernel(const float* __restrict__ p, const float* __restrict__ v,
           float* __restrict__ out)
{
    extern __shared__ char smem[];
    const uint32_t sb = smem_u32(smem);
    const int tid  = threadIdx.x;
    const int wid  = tid >> 5;       // 16 warps: m-row group
    const int lane = tid & 31;
    const int r    = lane >> 2;
    const int qc   = lane & 3;

    const int bh = blockIdx.y;
    const int b  = bh >> 3;
    const int h  = bh & 7;
    const int mt = blockIdx.x;       // 2 tiles of 256 rows

    const float* vbase = v + (size_t)b * L_ * H_ * E_ + h * E_;

    // ---- load V (512 x 64), transpose + split into Vt hi/lo [d][s] ----
#pragma unroll
    for (int i = tid; i < 8192; i += 512) {
        int s = i >> 4, d4 = i & 15;
        float4 vv = *(const float4*)(vbase + (size_t)s * (H_ * E_) + d4 * 4);
        float xs[4] = {vv.x, vv.y, vv.z, vv.w};
#pragma unroll
        for (int j = 0; j < 4; j++) {
            __nv_bfloat16 hb = __float2bfloat16(xs[j]);
            float hf = __bfloat162float(hb);
            __nv_bfloat16 lb = __float2bfloat16(xs[j] - hf);
            uint32_t off = (uint32_t)(d4 * 4 + j) * PVB_ST + s * 2;
            *(__nv_bfloat16*)(smem + PVB_HI + off) = hb;
            *(__nv_bfloat16*)(smem + PVB_LO + off) = lb;
        }
    }
    __syncthreads();

    // ---- mainloop: P from global, 3-product MMA ----
    const float* prow = p + ((size_t)bh * L_ + mt * 256 + wid * 16) * L_;

    float acc[8][4];
#pragma unroll
    for (int nb = 0; nb < 8; nb++)
#pragma unroll
        for (int x = 0; x < 4; x++) acc[nb][x] = 0.f;

#pragma unroll 4
    for (int ks = 0; ks < 32; ks++) {
        const int c0 = ks * 16 + qc * 2;
        float2 x00 = *(const float2*)(prow + (size_t)r * L_ + c0);
        float2 x01 = *(const float2*)(prow + (size_t)r * L_ + c0 + 8);
        float2 x10 = *(const float2*)(prow + (size_t)(r + 8) * L_ + c0);
        float2 x11 = *(const float2*)(prow + (size_t)(r + 8) * L_ + c0 + 8);

        uint32_t ahi[4], alo[4];
        split2(x00, ahi[0], alo[0]);
        split2(x10, ahi[1], alo[1]);
        split2(x01, ahi[2], alo[2]);
        split2(x11, ahi[3], alo[3]);

        const uint32_t kByte = (uint32_t)ks * 32 + qc * 4;
#pragma unroll
        for (int nb = 0; nb < 8; nb++) {
            uint32_t bd = sb + (uint32_t)(nb * 8 + r) * PVB_ST + kByte;
            uint32_t bhi[2], blo[2];
            bhi[0] = lds32(bd + PVB_HI);
            bhi[1] = lds32(bd + PVB_HI + 16);
            blo[0] = lds32(bd + PVB_LO);
            blo[1] = lds32(bd + PVB_LO + 16);
            mma16816(acc[nb], ahi, bhi);
            mma16816(acc[nb], alo, bhi);
            mma16816(acc[nb], ahi, blo);
        }
    }

    // ---- epilogue: direct fragment stores (quad -> full 32B sectors) ----
    const int l0 = mt * 256 + wid * 16 + r;
    float* ob0 = out + (((size_t)b * L_ + l0) * H_ + h) * E_ + qc * 2;
    float* ob1 = out + (((size_t)b * L_ + l0 + 8) * H_ + h) * E_ + qc * 2;
#pragma unroll
    for (int nb = 0; nb < 8; nb++) {
        *(float2*)(ob0 + nb * 8) = make_float2(acc[nb][0], acc[nb][1]);
        *(float2*)(ob1 + nb * 8) = make_float2(acc[nb][2], acc[nb][3]);
    }
}

// ======================================================================
extern "C" void kernel_launch(void* const* d_in, const int* in_sizes, int n_in,
                              void* d_out, int out_size)
{
    const float* q     = (const float*)d_in[0];
    const float* k     = (const float*)d_in[1];
    const float* v     = (const float*)d_in[2];
    const float* sigma = (const float*)d_in[3];

    float* out    = (float*)d_out;
    float* Vout   = out;                                        // [B,L,H,E]
    float* series = Vout + (size_t)B_ * L_ * H_ * E_;           // [B,H,L,L]
    float* prior  = series + (size_t)BH_ * L_ * L_;             // [B,H,L,L]
    float* sigf   = prior + (size_t)BH_ * L_ * L_;              // [B,H,L,L]

    cudaFuncSetAttribute(qk_softmax_kernel, cudaFuncAttributeMaxDynamicSharedMemorySize, F_SMEM);
    cudaFuncSetAttribute(pv2_kernel, cudaFuncAttributeMaxDynamicSharedMemorySize, PVB_SMEM);

    sig_precompute_kernel<<<BH_ * L_ / 256, 256>>>(sigma);

    dim3 g1(8, BH_);
    qk_softmax_kernel<<<g1, 512, F_SMEM>>>(q, k, series);

    prior_sig_kernel<<<(BH_ * L_) / 8, 256>>>(prior, sigf);

    dim3 g2(2, BH_);
    pv2_kernel<<<g2, 512, PVB_SMEM>>>(series, v, Vout);
}

// round 8
// speedup vs baseline: 1.9276x; 1.0794x over previous
#include <cuda_runtime.h>
#include <cuda_bf16.h>
#include <cstdint>

// Problem dims
#define B_ 16
#define L_ 512
#define H_ 8
#define E_ 64
#define BH_ (B_ * H_)          // 128

// precomputed bandwidth per (bh, l) row
__device__ float g_sg[BH_ * L_];

// ===================== helpers =====================
__device__ __forceinline__ uint32_t smem_u32(const void* p) {
    uint32_t a;
    asm("{ .reg .u64 t; cvta.to.shared.u64 t, %1; cvt.u32.u64 %0, t; }"
        : "=r"(a) : "l"(p));
    return a;
}
__device__ __forceinline__ uint32_t bf16x2_of(float v0, float v1) {
    uint32_t r;
    asm("cvt.rn.bf16x2.f32 %0, %1, %2;" : "=r"(r) : "f"(v1), "f"(v0));
    return r;
}
__device__ __forceinline__ uint32_t lds32(uint32_t addr) {
    uint32_t v;
    asm volatile("ld.shared.b32 %0, [%1];" : "=r"(v) : "r"(addr));
    return v;
}
__device__ __forceinline__ void mma16816(float* c, const uint32_t* a, const uint32_t* b) {
    asm volatile(
        "mma.sync.aligned.m16n8k16.row.col.f32.bf16.bf16.f32 "
        "{%0,%1,%2,%3}, {%4,%5,%6,%7}, {%8,%9}, {%0,%1,%2,%3};"
        : "+f"(c[0]), "+f"(c[1]), "+f"(c[2]), "+f"(c[3])
        : "r"(a[0]), "r"(a[1]), "r"(a[2]), "r"(a[3]), "r"(b[0]), "r"(b[1]));
}
__device__ __forceinline__ float exp_acc(float x) {
    float m = __fmul_rn(x, 1.4426950408889634f);
    float t = __fmaf_rn(x, 1.925962991e-8f, m);
    float r;
    asm("ex2.approx.ftz.f32 %0, %1;" : "=f"(r) : "f"(t));
    return r;
}
__device__ __forceinline__ void split_store4(char* smem, uint32_t offHi, uint32_t offLo, float4 v) {
    uint32_t h01 = bf16x2_of(v.x, v.y);
    uint32_t h23 = bf16x2_of(v.z, v.w);
    float l0 = v.x - __uint_as_float(h01 << 16);
    float l1 = v.y - __uint_as_float(h01 & 0xFFFF0000u);
    float l2 = v.z - __uint_as_float(h23 << 16);
    float l3 = v.w - __uint_as_float(h23 & 0xFFFF0000u);
    *(uint2*)(smem + offHi) = make_uint2(h01, h23);
    *(uint2*)(smem + offLo) = make_uint2(bf16x2_of(l0, l1), bf16x2_of(l2, l3));
}
__device__ __forceinline__ void split2(float2 v, uint32_t& hi, uint32_t& lo) {
    hi = bf16x2_of(v.x, v.y);
    float l0 = v.x - __uint_as_float(hi << 16);
    float l1 = v.y - __uint_as_float(hi & 0xFFFF0000u);
    lo = bf16x2_of(l0, l1);
}

// ======================================================================
// Kernel 0: precompute sg per (bh,l). Double-precision 3^s.
// ======================================================================
__global__ void __launch_bounds__(256) sig_precompute_kernel(const float* __restrict__ sigma)
{
    int idx = blockIdx.x * 256 + threadIdx.x;
    int bh = idx >> 9, l = idx & 511;
    int b = bh >> 3, h = bh & 7;
    double xd = (double)sigma[((size_t)b * L_ + l) * H_ + h];
    double sd = 1.0 / (1.0 + exp(-5.0 * xd));
    float sgm = (float)(sd + 1e-5);
    double P  = exp2((double)sgm * 1.5849625007211562);  // 3^sgm
    g_sg[idx] = (float)P - 1.0f;
}

// ======================================================================
// Kernel 1 (fused): series = softmax(QK^T/8); ALSO writes prior+sigf
// for its 64 rows (overlaps streaming writes with MMA compute).
// ======================================================================
#define F_ST   72
#define F_QHI  0
#define F_QLO  9216
#define F_KHI  18432
#define F_KLO  92160
#define F_RED0 165888
#define F_RED1 166912
#define F_SMEM 167936

__global__ void __launch_bounds__(512, 1)
qk_softmax_prior_kernel(const float* __restrict__ q, const float* __restrict__ k,
                        float* __restrict__ series,
                        float* __restrict__ prior, float* __restrict__ sigf)
{
    extern __shared__ char smem[];
    const uint32_t sb = smem_u32(smem);
    const int tid  = threadIdx.x;
    const int wid  = tid >> 5;
    const int lane = tid & 31;
    const int wm   = wid >> 2;
    const int wn   = wid & 3;
    const int r    = lane >> 2;
    const int qc   = lane & 3;

    const int bh = blockIdx.y;
    const int b  = bh >> 3;
    const int h  = bh & 7;
    const int lt = blockIdx.x;

    const float* qbase = q + (size_t)(b * L_ + lt * 64) * (H_ * E_) + h * E_;
    const float* kbase = k + (size_t)(b * L_) * (H_ * E_) + h * E_;

#pragma unroll
    for (int i = tid; i < 1024; i += 512) {
        int row = i >> 4, e4 = i & 15;
        uint32_t off = (uint32_t)row * (F_ST * 2) + e4 * 8;
        float4 va = *(const float4*)(qbase + (size_t)row * (H_ * E_) + e4 * 4);
        va.x *= 0.125f; va.y *= 0.125f; va.z *= 0.125f; va.w *= 0.125f;
        split_store4(smem, F_QHI + off, F_QLO + off, va);
    }
#pragma unroll
    for (int i = tid; i < 8192; i += 512) {
        int row = i >> 4, e4 = i & 15;
        uint32_t off = (uint32_t)row * (F_ST * 2) + e4 * 8;
        float4 vb = *(const float4*)(kbase + (size_t)row * (H_ * E_) + e4 * 4);
        split_store4(smem, F_KHI + off, F_KLO + off, vb);
    }
    __syncthreads();

    float acc[16][4];
#pragma unroll
    for (int nb = 0; nb < 16; nb++)
#pragma unroll
        for (int x = 0; x < 4; x++) acc[nb][x] = 0.f;

    const uint32_t abase[3] = {sb + F_QHI, sb + F_QHI, sb + F_QLO};
    const uint32_t bbase[3] = {sb + F_KHI, sb + F_KLO, sb + F_KHI};

#pragma unroll
    for (int pr = 0; pr < 3; pr++) {
        uint32_t Ab = abase[pr], Bb = bbase[pr];
#pragma unroll
        for (int ks = 0; ks < 4; ks++) {
            uint32_t kByte = ks * 32 + qc * 4;
            uint32_t a[4];
            uint32_t ad = Ab + (uint32_t)(wm * 16 + r) * (F_ST * 2) + kByte;
            a[0] = lds32(ad);
            a[1] = lds32(ad + 8 * F_ST * 2);
            a[2] = lds32(ad + 16);
            a[3] = lds32(ad + 8 * F_ST * 2 + 16);
#pragma unroll
            for (int nb = 0; nb < 16; nb++) {
                uint32_t bd = Bb + (uint32_t)(wn * 128 + nb * 8 + r) * (F_ST * 2) + kByte;
                uint32_t bf[2];
                bf[0] = lds32(bd);
                bf[1] = lds32(bd + 16);
                mma16816(acc[nb], a, bf);
            }
        }
    }

    const int row0 = wm * 16 + r;
    const int row1 = row0 + 8;

    float mx0 = -1e30f, mx1 = -1e30f;
#pragma unroll
    for (int nb = 0; nb < 16; nb++) {
        mx0 = fmaxf(mx0, fmaxf(acc[nb][0], acc[nb][1]));
        mx1 = fmaxf(mx1, fmaxf(acc[nb][2], acc[nb][3]));
    }
#pragma unroll
    for (int o = 1; o <= 2; o <<= 1) {
        mx0 = fmaxf(mx0, __shfl_xor_sync(0xffffffffu, mx0, o));
        mx1 = fmaxf(mx1, __shfl_xor_sync(0xffffffffu, mx1, o));
    }
    if (qc == 0) {
        *(float*)(smem + F_RED0 + (row0 * 4 + wn) * 4) = mx0;
        *(float*)(smem + F_RED0 + (row1 * 4 + wn) * 4) = mx1;
    }
    __syncthreads();
    {
        const float* rd = (const float*)(smem + F_RED0);
        mx0 = fmaxf(fmaxf(rd[row0 * 4 + 0], rd[row0 * 4 + 1]),
                    fmaxf(rd[row0 * 4 + 2], rd[row0 * 4 + 3]));
        mx1 = fmaxf(fmaxf(rd[row1 * 4 + 0], rd[row1 * 4 + 1]),
                    fmaxf(rd[row1 * 4 + 2], rd[row1 * 4 + 3]));
    }

    float s0 = 0.f, s1 = 0.f;
#pragma unroll
    for (int nb = 0; nb < 16; nb++) {
        acc[nb][0] = exp_acc(acc[nb][0] - mx0); s0 += acc[nb][0];
        acc[nb][1] = exp_acc(acc[nb][1] - mx0); s0 += acc[nb][1];
        acc[nb][2] = exp_acc(acc[nb][2] - mx1); s1 += acc[nb][2];
        acc[nb][3] = exp_acc(acc[nb][3] - mx1); s1 += acc[nb][3];
    }
#pragma unroll
    for (int o = 1; o <= 2; o <<= 1) {
        s0 += __shfl_xor_sync(0xffffffffu, s0, o);
        s1 += __shfl_xor_sync(0xffffffffu, s1, o);
    }
    if (qc == 0) {
        *(float*)(smem + F_RED1 + (row0 * 4 + wn) * 4) = s0;
        *(float*)(smem + F_RED1 + (row1 * 4 + wn) * 4) = s1;
    }
    __syncthreads();
    {
        const float* rd = (const float*)(smem + F_RED1);
        s0 = (rd[row0 * 4 + 0] + rd[row0 * 4 + 1]) + (rd[row0 * 4 + 2] + rd[row0 * 4 + 3]);
        s1 = (rd[row1 * 4 + 0] + rd[row1 * 4 + 1]) + (rd[row1 * 4 + 2] + rd[row1 * 4 + 3]);
    }
    const float inv0 = __fdiv_rn(1.f, s0);
    const float inv1 = __fdiv_rn(1.f, s1);

    float* o0 = series + ((size_t)bh * L_ + lt * 64 + row0) * L_ + wn * 128 + qc * 2;
    float* o1 = series + ((size_t)bh * L_ + lt * 64 + row1) * L_ + wn * 128 + qc * 2;
#pragma unroll
    for (int nb = 0; nb < 16; nb++) {
        *(float2*)(o0 + nb * 8) = make_float2(acc[nb][0] * inv0, acc[nb][1] * inv0);
        *(float2*)(o1 + nb * 8) = make_float2(acc[nb][2] * inv1, acc[nb][3] * inv1);
    }

    // ---------- prior + sigma_full for the same rows ----------
    const int gl0 = lt * 64 + row0;
    const int gl1 = lt * 64 + row1;
    const float sg0 = g_sg[bh * L_ + gl0];
    const float sg1 = g_sg[bh * L_ + gl1];
    const float c0v   = __fdiv_rn(0.3989422804014327f, sg0);
    const float rinv0 = __fdiv_rn(1.0f, __fmul_rn(2.0f, __fmul_rn(sg0, sg0)));
    const float c1v   = __fdiv_rn(0.3989422804014327f, sg1);
    const float rinv1 = __fdiv_rn(1.0f, __fmul_rn(2.0f, __fmul_rn(sg1, sg1)));

    float* pr0 = prior + ((size_t)bh * L_ + gl0) * L_ + wn * 128 + qc * 2;
    float* pr1 = prior + ((size_t)bh * L_ + gl1) * L_ + wn * 128 + qc * 2;
    float* sf0 = sigf + ((size_t)bh * L_ + gl0) * L_ + wn * 128 + qc * 2;
    float* sf1 = sigf + ((size_t)bh * L_ + gl1) * L_ + wn * 128 + qc * 2;
#pragma unroll
    for (int nb = 0; nb < 16; nb++) {
        int j = wn * 128 + nb * 8 + qc * 2;
        float dA0 = (float)(gl0 - j),     dA1 = (float)(gl0 - j - 1);
        float dB0 = (float)(gl1 - j),     dB1 = (float)(gl1 - j - 1);
        float2 pA, pB;
        pA.x = __fmul_rn(c0v, exp_acc(-__fmul_rn(__fmul_rn(dA0, dA0), rinv0)));
        pA.y = __fmul_rn(c0v, exp_acc(-__fmul_rn(__fmul_rn(dA1, dA1), rinv0)));
        pB.x = __fmul_rn(c1v, exp_acc(-__fmul_rn(__fmul_rn(dB0, dB0), rinv1)));
        pB.y = __fmul_rn(c1v, exp_acc(-__fmul_rn(__fmul_rn(dB1, dB1), rinv1)));
        *(float2*)(pr0 + nb * 8) = pA;
        *(float2*)(pr1 + nb * 8) = pB;
        *(float2*)(sf0 + nb * 8) = make_float2(sg0, sg0);
        *(float2*)(sf1 + nb * 8) = make_float2(sg1, sg1);
    }
}

// ======================================================================
// Kernel 3 (pv3): V[b,l,h,d] = sum_s P[bh,l,s] * values[b,s,h,d]
// One CTA per bh: 512 l-rows x 64 d, 512 thr, warp = 32 rows (2 m-frags).
// Grid = 128 -> single wave. B frags loaded per-nb (low reg pressure).
// ======================================================================
#define PVB_ST  1040
#define PVB_HI  0
#define PVB_LO  66560
#define PVB_SMEM 133120

__global__ void __launch_bounds__(512, 1)
pv3_kernel(const float* __restrict__ p, const float* __restrict__ v,
           float* __restrict__ out)
{
    extern __shared__ char smem[];
    const uint32_t sb = smem_u32(smem);
    const int tid  = threadIdx.x;
    const int wid  = tid >> 5;       // 16 warps x 32 rows = 512 rows
    const int lane = tid & 31;
    const int r    = lane >> 2;
    const int qc   = lane & 3;

    const int bh = blockIdx.x;
    const int b  = bh >> 3;
    const int h  = bh & 7;

    const float* vbase = v + (size_t)b * L_ * H_ * E_ + h * E_;

    // ---- load V (512 x 64), transpose + split into Vt hi/lo [d][s] ----
#pragma unroll
    for (int i = tid; i < 8192; i += 512) {
        int s = i >> 4, d4 = i & 15;
        float4 vv = *(const float4*)(vbase + (size_t)s * (H_ * E_) + d4 * 4);
        float xs[4] = {vv.x, vv.y, vv.z, vv.w};
#pragma unroll
        for (int j = 0; j < 4; j++) {
            __nv_bfloat16 hb = __float2bfloat16(xs[j]);
            float hf = __bfloat162float(hb);
            __nv_bfloat16 lb = __float2bfloat16(xs[j] - hf);
            uint32_t off = (uint32_t)(d4 * 4 + j) * PVB_ST + s * 2;
            *(__nv_bfloat16*)(smem + PVB_HI + off) = hb;
            *(__nv_bfloat16*)(smem + PVB_LO + off) = lb;
        }
    }
    __syncthreads();

    const float* prow = p + ((size_t)bh * L_ + wid * 32) * L_;

    float acc[2][8][4];
#pragma unroll
    for (int m = 0; m < 2; m++)
#pragma unroll
        for (int nb = 0; nb < 8; nb++)
#pragma unroll
            for (int x = 0; x < 4; x++) acc[m][nb][x] = 0.f;

#pragma unroll 2
    for (int ks = 0; ks < 32; ks++) {
        const int c0 = ks * 16 + qc * 2;
        uint32_t ahi[2][4], alo[2][4];
#pragma unroll
        for (int m = 0; m < 2; m++) {
            float2 x0 = *(const float2*)(prow + (size_t)(m * 16 + r) * L_ + c0);
            float2 x1 = *(const float2*)(prow + (size_t)(m * 16 + r + 8) * L_ + c0);
            float2 x2 = *(const float2*)(prow + (size_t)(m * 16 + r) * L_ + c0 + 8);
            float2 x3 = *(const float2*)(prow + (size_t)(m * 16 + r + 8) * L_ + c0 + 8);
            split2(x0, ahi[m][0], alo[m][0]);
            split2(x1, ahi[m][1], alo[m][1]);
            split2(x2, ahi[m][2], alo[m][2]);
            split2(x3, ahi[m][3], alo[m][3]);
        }

        const uint32_t kByte = (uint32_t)ks * 32 + qc * 4;
#pragma unroll
        for (int nb = 0; nb < 8; nb++) {
            uint32_t bd = sb + (uint32_t)(nb * 8 + r) * PVB_ST + kByte;
            uint32_t bhi[2], blo[2];
            bhi[0] = lds32(bd + PVB_HI);
            bhi[1] = lds32(bd + PVB_HI + 16);
            blo[0] = lds32(bd + PVB_LO);
            blo[1] = lds32(bd + PVB_LO + 16);
#pragma unroll
            for (int m = 0; m < 2; m++) {
                mma16816(acc[m][nb], ahi[m], bhi);
                mma16816(acc[m][nb], alo[m], bhi);
                mma16816(acc[m][nb], ahi[m], blo);
            }
        }
    }

    // ---- epilogue ----
#pragma unroll
    for (int m = 0; m < 2; m++) {
        const int l0 = wid * 32 + m * 16 + r;
        float* ob0 = out + (((size_t)b * L_ + l0) * H_ + h) * E_ + qc * 2;
        float* ob1 = out + (((size_t)b * L_ + l0 + 8) * H_ + h) * E_ + qc * 2;
#pragma unroll
        for (int nb = 0; nb < 8; nb++) {
            *(float2*)(ob0 + nb * 8) = make_float2(acc[m][nb][0], acc[m][nb][1]);
            *(float2*)(ob1 + nb * 8) = make_float2(acc[m][nb][2], acc[m][nb][3]);
        }
    }
}

// ======================================================================
extern "C" void kernel_launch(void* const* d_in, const int* in_sizes, int n_in,
                              void* d_out, int out_size)
{
    const float* q     = (const float*)d_in[0];
    const float* k     = (const float*)d_in[1];
    const float* v     = (const float*)d_in[2];
    const float* sigma = (const float*)d_in[3];

    float* out    = (float*)d_out;
    float* Vout   = out;                                        // [B,L,H,E]
    float* series = Vout + (size_t)B_ * L_ * H_ * E_;           // [B,H,L,L]
    float* prior  = series + (size_t)BH_ * L_ * L_;             // [B,H,L,L]
    float* sigf   = prior + (size_t)BH_ * L_ * L_;              // [B,H,L,L]

    cudaFuncSetAttribute(qk_softmax_prior_kernel, cudaFuncAttributeMaxDynamicSharedMemorySize, F_SMEM);
    cudaFuncSetAttribute(pv3_kernel, cudaFuncAttributeMaxDynamicSharedMemorySize, PVB_SMEM);

    sig_precompute_kernel<<<BH_ * L_ / 256, 256>>>(sigma);

    dim3 g1(8, BH_);
    qk_softmax_prior_kernel<<<g1, 512, F_SMEM>>>(q, k, series, prior, sigf);

    pv3_kernel<<<BH_, 512, PVB_SMEM>>>(series, v, Vout);
}

// round 9
// speedup vs baseline: 2.0622x; 1.0698x over previous
#include <cuda_runtime.h>
#include <cuda_bf16.h>
#include <cstdint>

// Problem dims
#define B_ 16
#define L_ 512
#define H_ 8
#define E_ 64
#define BH_ (B_ * H_)          // 128

// ===================== helpers =====================
__device__ __forceinline__ uint32_t smem_u32(const void* p) {
    uint32_t a;
    asm("{ .reg .u64 t; cvta.to.shared.u64 t, %1; cvt.u32.u64 %0, t; }"
        : "=r"(a) : "l"(p));
    return a;
}
__device__ __forceinline__ uint32_t bf16x2_of(float v0, float v1) {
    uint32_t r;
    asm("cvt.rn.bf16x2.f32 %0, %1, %2;" : "=r"(r) : "f"(v1), "f"(v0));
    return r;
}
__device__ __forceinline__ uint32_t lds32(uint32_t addr) {
    uint32_t v;
    asm volatile("ld.shared.b32 %0, [%1];" : "=r"(v) : "r"(addr));
    return v;
}
__device__ __forceinline__ void mma16816(float* c, const uint32_t* a, const uint32_t* b) {
    asm volatile(
        "mma.sync.aligned.m16n8k16.row.col.f32.bf16.bf16.f32 "
        "{%0,%1,%2,%3}, {%4,%5,%6,%7}, {%8,%9}, {%0,%1,%2,%3};"
        : "+f"(c[0]), "+f"(c[1]), "+f"(c[2]), "+f"(c[3])
        : "r"(a[0]), "r"(a[1]), "r"(a[2]), "r"(a[3]), "r"(b[0]), "r"(b[1]));
}
__device__ __forceinline__ float exp_acc(float x) {
    float m = __fmul_rn(x, 1.4426950408889634f);
    float t = __fmaf_rn(x, 1.925962991e-8f, m);
    float r;
    asm("ex2.approx.ftz.f32 %0, %1;" : "=f"(r) : "f"(t));
    return r;
}
__device__ __forceinline__ void split_store4(char* smem, uint32_t offHi, uint32_t offLo, float4 v) {
    uint32_t h01 = bf16x2_of(v.x, v.y);
    uint32_t h23 = bf16x2_of(v.z, v.w);
    float l0 = v.x - __uint_as_float(h01 << 16);
    float l1 = v.y - __uint_as_float(h01 & 0xFFFF0000u);
    float l2 = v.z - __uint_as_float(h23 << 16);
    float l3 = v.w - __uint_as_float(h23 & 0xFFFF0000u);
    *(uint2*)(smem + offHi) = make_uint2(h01, h23);
    *(uint2*)(smem + offLo) = make_uint2(bf16x2_of(l0, l1), bf16x2_of(l2, l3));
}
__device__ __forceinline__ void split2(float2 v, uint32_t& hi, uint32_t& lo) {
    hi = bf16x2_of(v.x, v.y);
    float l0 = v.x - __uint_as_float(hi << 16);
    float l1 = v.y - __uint_as_float(hi & 0xFFFF0000u);
    lo = bf16x2_of(l0, l1);
}

// ======================================================================
// Kernel 1 (fused): sg (fp64, in-CTA) + prior + sigf + QK^T MMA +
// softmax + series. prior/sigf stores issued BEFORE the MMA loop so
// DRAM drains during tensor compute.
// ======================================================================
#define F_ST   72
#define F_QHI  0
#define F_QLO  9216
#define F_KHI  18432
#define F_KLO  92160
#define F_SG   165888            // 64 * 4 = 256
#define F_RED0 166144
#define F_RED1 167168
#define F_SMEM 168192

__global__ void __launch_bounds__(512, 1)
qk_softmax_prior_kernel(const float* __restrict__ q, const float* __restrict__ k,
                        const float* __restrict__ sigma,
                        float* __restrict__ series,
                        float* __restrict__ prior, float* __restrict__ sigf)
{
    extern __shared__ char smem[];
    const uint32_t sb = smem_u32(smem);
    const int tid  = threadIdx.x;
    const int wid  = tid >> 5;
    const int lane = tid & 31;
    const int wm   = wid >> 2;
    const int wn   = wid & 3;
    const int r    = lane >> 2;
    const int qc   = lane & 3;

    const int bh = blockIdx.y;
    const int b  = bh >> 3;
    const int h  = bh & 7;
    const int lt = blockIdx.x;

    // ---- sigma -> bandwidth for this CTA's 64 rows (fp64, 64 threads) ----
    if (tid < 64) {
        int gl = lt * 64 + tid;
        double xd = (double)sigma[((size_t)b * L_ + gl) * H_ + h];
        double sd = 1.0 / (1.0 + exp(-5.0 * xd));
        float sgm = (float)(sd + 1e-5);
        double P  = exp2((double)sgm * 1.5849625007211562);  // 3^sgm
        *(float*)(smem + F_SG + tid * 4) = (float)P - 1.0f;
    }

    const float* qbase = q + (size_t)(b * L_ + lt * 64) * (H_ * E_) + h * E_;
    const float* kbase = k + (size_t)(b * L_) * (H_ * E_) + h * E_;

#pragma unroll
    for (int i = tid; i < 1024; i += 512) {
        int row = i >> 4, e4 = i & 15;
        uint32_t off = (uint32_t)row * (F_ST * 2) + e4 * 8;
        float4 va = *(const float4*)(qbase + (size_t)row * (H_ * E_) + e4 * 4);
        va.x *= 0.125f; va.y *= 0.125f; va.z *= 0.125f; va.w *= 0.125f;
        split_store4(smem, F_QHI + off, F_QLO + off, va);
    }
#pragma unroll
    for (int i = tid; i < 8192; i += 512) {
        int row = i >> 4, e4 = i & 15;
        uint32_t off = (uint32_t)row * (F_ST * 2) + e4 * 8;
        float4 vb = *(const float4*)(kbase + (size_t)row * (H_ * E_) + e4 * 4);
        split_store4(smem, F_KHI + off, F_KLO + off, vb);
    }
    __syncthreads();

    // ---- prior + sigma_full FIRST (stores drain during MMA phase) ----
    // linear row-major float4 stores: 64 rows x 512 cols
    {
        const int lbase = lt * 64;
#pragma unroll
        for (int i = tid; i < 8192; i += 512) {
            int row = i >> 7, c4 = (i & 127) * 4;
            const float sg = *(const float*)(smem + F_SG + row * 4);
            const float cv   = __fdiv_rn(0.3989422804014327f, sg);
            const float rinv = __fdiv_rn(1.0f, __fmul_rn(2.0f, __fmul_rn(sg, sg)));
            const int gl = lbase + row;
            float d0 = (float)(gl - c4);
            float d1 = (float)(gl - c4 - 1);
            float d2 = (float)(gl - c4 - 2);
            float d3 = (float)(gl - c4 - 3);
            float4 pv;
            pv.x = __fmul_rn(cv, exp_acc(-__fmul_rn(__fmul_rn(d0, d0), rinv)));
            pv.y = __fmul_rn(cv, exp_acc(-__fmul_rn(__fmul_rn(d1, d1), rinv)));
            pv.z = __fmul_rn(cv, exp_acc(-__fmul_rn(__fmul_rn(d2, d2), rinv)));
            pv.w = __fmul_rn(cv, exp_acc(-__fmul_rn(__fmul_rn(d3, d3), rinv)));
            size_t base = ((size_t)bh * L_ + gl) * L_ + c4;
            *(float4*)(prior + base) = pv;
            *(float4*)(sigf + base)  = make_float4(sg, sg, sg, sg);
        }
    }

    // ---- QK^T MMA (3-product bf16 split) ----
    float acc[16][4];
#pragma unroll
    for (int nb = 0; nb < 16; nb++)
#pragma unroll
        for (int x = 0; x < 4; x++) acc[nb][x] = 0.f;

    const uint32_t abase[3] = {sb + F_QHI, sb + F_QHI, sb + F_QLO};
    const uint32_t bbase[3] = {sb + F_KHI, sb + F_KLO, sb + F_KHI};

#pragma unroll
    for (int pr = 0; pr < 3; pr++) {
        uint32_t Ab = abase[pr], Bb = bbase[pr];
#pragma unroll
        for (int ks = 0; ks < 4; ks++) {
            uint32_t kByte = ks * 32 + qc * 4;
            uint32_t a[4];
            uint32_t ad = Ab + (uint32_t)(wm * 16 + r) * (F_ST * 2) + kByte;
            a[0] = lds32(ad);
            a[1] = lds32(ad + 8 * F_ST * 2);
            a[2] = lds32(ad + 16);
            a[3] = lds32(ad + 8 * F_ST * 2 + 16);
#pragma unroll
            for (int nb = 0; nb < 16; nb++) {
                uint32_t bd = Bb + (uint32_t)(wn * 128 + nb * 8 + r) * (F_ST * 2) + kByte;
                uint32_t bf[2];
                bf[0] = lds32(bd);
                bf[1] = lds32(bd + 16);
                mma16816(acc[nb], a, bf);
            }
        }
    }

    // ---- softmax over 512 cols ----
    const int row0 = wm * 16 + r;
    const int row1 = row0 + 8;

    float mx0 = -1e30f, mx1 = -1e30f;
#pragma unroll
    for (int nb = 0; nb < 16; nb++) {
        mx0 = fmaxf(mx0, fmaxf(acc[nb][0], acc[nb][1]));
        mx1 = fmaxf(mx1, fmaxf(acc[nb][2], acc[nb][3]));
    }
#pragma unroll
    for (int o = 1; o <= 2; o <<= 1) {
        mx0 = fmaxf(mx0, __shfl_xor_sync(0xffffffffu, mx0, o));
        mx1 = fmaxf(mx1, __shfl_xor_sync(0xffffffffu, mx1, o));
    }
    if (qc == 0) {
        *(float*)(smem + F_RED0 + (row0 * 4 + wn) * 4) = mx0;
        *(float*)(smem + F_RED0 + (row1 * 4 + wn) * 4) = mx1;
    }
    __syncthreads();
    {
        const float* rd = (const float*)(smem + F_RED0);
        mx0 = fmaxf(fmaxf(rd[row0 * 4 + 0], rd[row0 * 4 + 1]),
                    fmaxf(rd[row0 * 4 + 2], rd[row0 * 4 + 3]));
        mx1 = fmaxf(fmaxf(rd[row1 * 4 + 0], rd[row1 * 4 + 1]),
                    fmaxf(rd[row1 * 4 + 2], rd[row1 * 4 + 3]));
    }

    float s0 = 0.f, s1 = 0.f;
#pragma unroll
    for (int nb = 0; nb < 16; nb++) {
        acc[nb][0] = exp_acc(acc[nb][0] - mx0); s0 += acc[nb][0];
        acc[nb][1] = exp_acc(acc[nb][1] - mx0); s0 += acc[nb][1];
        acc[nb][2] = exp_acc(acc[nb][2] - mx1); s1 += acc[nb][2];
        acc[nb][3] = exp_acc(acc[nb][3] - mx1); s1 += acc[nb][3];
    }
#pragma unroll
    for (int o = 1; o <= 2; o <<= 1) {
        s0 += __shfl_xor_sync(0xffffffffu, s0, o);
        s1 += __shfl_xor_sync(0xffffffffu, s1, o);
    }
    if (qc == 0) {
        *(float*)(smem + F_RED1 + (row0 * 4 + wn) * 4) = s0;
        *(float*)(smem + F_RED1 + (row1 * 4 + wn) * 4) = s1;
    }
    __syncthreads();
    {
        const float* rd = (const float*)(smem + F_RED1);
        s0 = (rd[row0 * 4 + 0] + rd[row0 * 4 + 1]) + (rd[row0 * 4 + 2] + rd[row0 * 4 + 3]);
        s1 = (rd[row1 * 4 + 0] + rd[row1 * 4 + 1]) + (rd[row1 * 4 + 2] + rd[row1 * 4 + 3]);
    }
    const float inv0 = __fdiv_rn(1.f, s0);
    const float inv1 = __fdiv_rn(1.f, s1);

    float* o0 = series + ((size_t)bh * L_ + lt * 64 + row0) * L_ + wn * 128 + qc * 2;
    float* o1 = series + ((size_t)bh * L_ + lt * 64 + row1) * L_ + wn * 128 + qc * 2;
#pragma unroll
    for (int nb = 0; nb < 16; nb++) {
        *(float2*)(o0 + nb * 8) = make_float2(acc[nb][0] * inv0, acc[nb][1] * inv0);
        *(float2*)(o1 + nb * 8) = make_float2(acc[nb][2] * inv1, acc[nb][3] * inv1);
    }
}

// ======================================================================
// Kernel 3 (pv3): V[b,l,h,d] = sum_s P[bh,l,s] * values[b,s,h,d]
// One CTA per bh: 512 l-rows x 64 d, 512 thr, warp = 32 rows.
// ======================================================================
#define PVB_ST  1040
#define PVB_HI  0
#define PVB_LO  66560
#define PVB_SMEM 133120

__global__ void __launch_bounds__(512, 1)
pv3_kernel(const float* __restrict__ p, const float* __restrict__ v,
           float* __restrict__ out)
{
    extern __shared__ char smem[];
    const uint32_t sb = smem_u32(smem);
    const int tid  = threadIdx.x;
    const int wid  = tid >> 5;
    const int lane = tid & 31;
    const int r    = lane >> 2;
    const int qc   = lane & 3;

    const int bh = blockIdx.x;
    const int b  = bh >> 3;
    const int h  = bh & 7;

    const float* vbase = v + (size_t)b * L_ * H_ * E_ + h * E_;

#pragma unroll
    for (int i = tid; i < 8192; i += 512) {
        int s = i >> 4, d4 = i & 15;
        float4 vv = *(const float4*)(vbase + (size_t)s * (H_ * E_) + d4 * 4);
        float xs[4] = {vv.x, vv.y, vv.z, vv.w};
#pragma unroll
        for (int j = 0; j < 4; j++) {
            __nv_bfloat16 hb = __float2bfloat16(xs[j]);
            float hf = __bfloat162float(hb);
            __nv_bfloat16 lb = __float2bfloat16(xs[j] - hf);
            uint32_t off = (uint32_t)(d4 * 4 + j) * PVB_ST + s * 2;
            *(__nv_bfloat16*)(smem + PVB_HI + off) = hb;
            *(__nv_bfloat16*)(smem + PVB_LO + off) = lb;
        }
    }
    __syncthreads();

    const float* prow = p + ((size_t)bh * L_ + wid * 32) * L_;

    float acc[2][8][4];
#pragma unroll
    for (int m = 0; m < 2; m++)
#pragma unroll
        for (int nb = 0; nb < 8; nb++)
#pragma unroll
            for (int x = 0; x < 4; x++) acc[m][nb][x] = 0.f;

#pragma unroll 2
    for (int ks = 0; ks < 32; ks++) {
        const int c0 = ks * 16 + qc * 2;
        uint32_t ahi[2][4], alo[2][4];
#pragma unroll
        for (int m = 0; m < 2; m++) {
            float2 x0 = *(const float2*)(prow + (size_t)(m * 16 + r) * L_ + c0);
            float2 x1 = *(const float2*)(prow + (size_t)(m * 16 + r + 8) * L_ + c0);
            float2 x2 = *(const float2*)(prow + (size_t)(m * 16 + r) * L_ + c0 + 8);
            float2 x3 = *(const float2*)(prow + (size_t)(m * 16 + r + 8) * L_ + c0 + 8);
            split2(x0, ahi[m][0], alo[m][0]);
            split2(x1, ahi[m][1], alo[m][1]);
            split2(x2, ahi[m][2], alo[m][2]);
            split2(x3, ahi[m][3], alo[m][3]);
        }

        const uint32_t kByte = (uint32_t)ks * 32 + qc * 4;
#pragma unroll
        for (int nb = 0; nb < 8; nb++) {
            uint32_t bd = sb + (uint32_t)(nb * 8 + r) * PVB_ST + kByte;
            uint32_t bhi[2], blo[2];
            bhi[0] = lds32(bd + PVB_HI);
            bhi[1] = lds32(bd + PVB_HI + 16);
            blo[0] = lds32(bd + PVB_LO);
            blo[1] = lds32(bd + PVB_LO + 16);
#pragma unroll
            for (int m = 0; m < 2; m++) {
                mma16816(acc[m][nb], ahi[m], bhi);
                mma16816(acc[m][nb], alo[m], bhi);
                mma16816(acc[m][nb], ahi[m], blo);
            }
        }
    }

#pragma unroll
    for (int m = 0; m < 2; m++) {
        const int l0 = wid * 32 + m * 16 + r;
        float* ob0 = out + (((size_t)b * L_ + l0) * H_ + h) * E_ + qc * 2;
        float* ob1 = out + (((size_t)b * L_ + l0 + 8) * H_ + h) * E_ + qc * 2;
#pragma unroll
        for (int nb = 0; nb < 8; nb++) {
            *(float2*)(ob0 + nb * 8) = make_float2(acc[m][nb][0], acc[m][nb][1]);
            *(float2*)(ob1 + nb * 8) = make_float2(acc[m][nb][2], acc[m][nb][3]);
        }
    }
}

// ======================================================================
extern "C" void kernel_launch(void* const* d_in, const int* in_sizes, int n_in,
                              void* d_out, int out_size)
{
    const float* q     = (const float*)d_in[0];
    const float* k     = (const float*)d_in[1];
    const float* v     = (const float*)d_in[2];
    const float* sigma = (const float*)d_in[3];

    float* out    = (float*)d_out;
    float* Vout   = out;                                        // [B,L,H,E]
    float* series = Vout + (size_t)B_ * L_ * H_ * E_;           // [B,H,L,L]
    float* prior  = series + (size_t)BH_ * L_ * L_;             // [B,H,L,L]
    float* sigf   = prior + (size_t)BH_ * L_ * L_;              // [B,H,L,L]

    cudaFuncSetAttribute(qk_softmax_prior_kernel, cudaFuncAttributeMaxDynamicSharedMemorySize, F_SMEM);
    cudaFuncSetAttribute(pv3_kernel, cudaFuncAttributeMaxDynamicSharedMemorySize, PVB_SMEM);

    dim3 g1(8, BH_);
    qk_softmax_prior_kernel<<<g1, 512, F_SMEM>>>(q, k, sigma, series, prior, sigf);

    pv3_kernel<<<BH_, 512, PVB_SMEM>>>(series, v, Vout);
}